// round 10
// baseline (speedup 1.0000x reference)
#include <cuda_runtime.h>

#define NB 16
#define NT 50
#define NG 64
#define NA 3
#define NCH 96
#define NCLS 91
#define NCELL (NB*NA*NG*NG)   /* 196608 */

#define OBJ_BLOCKS 256        /* 256 thr: (b, ALL 3 anchors, 4 jj rows, all ii) */
#define TGT_BLOCKS 16         /* one block per batch */
#define TOT_BLOCKS (OBJ_BLOCKS + TGT_BLOCKS)
#define WIN_PER_B  16         /* 64 jj rows / 4 */

// ANCHORS / STRIDE(8)
__constant__ float c_aw[9] = {1.25f, 2.0f, 4.125f, 3.75f, 7.75f, 7.375f, 14.5f, 19.5f, 46.625f};
__constant__ float c_ah[9] = {1.625f, 3.75f, 2.875f, 7.625f, 5.625f, 14.875f, 11.25f, 24.75f, 40.75f};

// Grid-wide accumulator (zero-init at load; last block resets each call)
__device__ float    g_acc;
__device__ unsigned g_cnt;

__device__ __forceinline__ float softplusf(float x) {
    return fmaxf(x, 0.f) + __logf(1.f + __expf(-fabsf(x)));
}
__device__ __forceinline__ float sigmoidf(float x) {
    return __fdividef(1.f, 1.f + __expf(-x));
}

struct TInfo {
    float tx, ty, tw, th;
    int   a, cls, cell;
    bool  valid, mask;
};

__device__ __forceinline__ TInfo target_info(const float* __restrict__ labels,
                                             int b, int tl) {
    const float* L = labels + (size_t)(b * NT + tl) * 5;
    float cls = L[0], x = L[1], y = L[2], w = L[3], h = L[4];
    TInfo r;
    r.valid = (cls + x + y + w + h) > 0.f;
    r.tx = x * NG; r.ty = y * NG; r.tw = w * NG; r.th = h * NG;
    float at = r.tw * r.th;
    float best = -1e30f; int bi = 0;
#pragma unroll
    for (int k = 0; k < 9; k++) {
        float mw = fminf(r.tw, c_aw[k]);
        float mh = fminf(r.th, c_ah[k]);
        float inter = (mw > 0.f && mh > 0.f) ? mw * mh : 0.f;
        float iou = inter / (at + c_aw[k] * c_ah[k] - inter);
        if (iou > best) { best = iou; bi = k; }
    }
    r.a = bi % 3;
    r.mask = r.valid && (bi < 3);      // ANCH_MASK = [0,1,2] at SCALE=2
    int ii = (int)r.tx, jj = (int)r.ty;
    r.cell = ((b * NA + r.a) * NG + jj) * NG + ii;
    r.cls = (int)cls;
    return r;
}

__global__ void __launch_bounds__(256) k_one(const float* __restrict__ out,
                                             const float* __restrict__ labels,
                                             float* __restrict__ res) {
    int tid = threadIdx.x;

    if (blockIdx.x < OBJ_BLOCKS) {
        // ── Obj-loss: one thread owns the SAME (jj,ii) site in all 3 anchor
        //    planes, so each target's SMEM read + loop overhead is amortized 3×.
        __shared__ float4 s_tb[NT];
        __shared__ float  s_a3[NT];
        __shared__ unsigned char s_flag[3 * 256];
        __shared__ float  s_red[8];

        int b   = blockIdx.x >> 4;          // / WIN_PER_B
        int wb  = blockIdx.x & 15;
        int jj0 = wb * 4;
        int ii  = tid & 63;
        int jr  = tid >> 6;                 // 0..3
        int jj  = jj0 + jr;

        // Cell indices for the 3 anchor planes (4096 cells apart)
        int cell0 = ((b * NA + 0) * NG + jj) * NG + ii;

        // Issue all 6 loads FIRST (independent, in flight during staging)
        float4 ov[3]; float o4[3];
#pragma unroll
        for (int a = 0; a < 3; a++) {
            const float* o = out + (size_t)(cell0 + a * (NG * NG)) * NCH;
            ov[a] = __ldg(reinterpret_cast<const float4*>(o));  // ch0..3
            o4[a] = __ldg(o + 4);
        }

        // Stage this batch's 50 target boxes; flag local target cells
        s_flag[tid] = 0; s_flag[tid + 256] = 0; s_flag[tid + 512] = 0;
        if (tid < NT) {
            TInfo t = target_info(labels, b, tid);
            if (t.valid) {
                s_tb[tid] = make_float4(t.tx - 0.5f * t.tw, t.ty - 0.5f * t.th,
                                        t.tx + 0.5f * t.tw, t.ty + 0.5f * t.th);
                s_a3[tid] = t.tw * t.th * (1.f / 3.f);
            } else {
                s_tb[tid] = make_float4(1e30f, 1e30f, -1e30f, -1e30f);
                s_a3[tid] = 1e30f;   // sentinel: never wins the running max
            }
            if (t.mask) {
                int jt = (t.cell >> 6) & 63, it = t.cell & 63;
                int jr_t = jt - jj0;
                if (jr_t >= 0 && jr_t < 4)
                    s_flag[t.a * 256 + jr_t * 64 + it] = 1;
            }
        }
        __syncthreads();

        // Pred boxes for the 3 anchor cells
        float ptlx[3], ptly[3], pbrx[3], pbry[3], ap3[3], acc[3];
#pragma unroll
        for (int a = 0; a < 3; a++) {
            float px = sigmoidf(ov[a].x) + (float)ii;
            float py = sigmoidf(ov[a].y) + (float)jj;
            float pw = __expf(ov[a].z) * c_aw[a];
            float ph = __expf(ov[a].w) * c_ah[a];
            ptlx[a] = px - 0.5f * pw;  pbrx[a] = px + 0.5f * pw;
            ptly[a] = py - 0.5f * ph;  pbry[a] = py + 0.5f * ph;
            ap3[a]  = pw * ph * (1.f / 3.f);
            acc[a]  = -1e30f;
        }

        // ignored  <=>  max_q( max(dx,0)*dy - at_q/3 ) > ap/3
        // (single clamp suffices: if dy<0 then dxp*dy <= 0 < ap3)
#pragma unroll 5
        for (int q = 0; q < NT; q++) {
            float4 tb = s_tb[q];
            float  s3 = s_a3[q];
#pragma unroll
            for (int a = 0; a < 3; a++) {
                float dx  = fminf(pbrx[a], tb.z) - fmaxf(ptlx[a], tb.x);
                float dxp = fmaxf(dx, 0.f);
                float dy  = fminf(pbry[a], tb.w) - fmaxf(ptly[a], tb.y);
                acc[a] = fmaxf(acc[a], fmaf(dxp, dy, -s3));
            }
        }

        float contrib = 0.f;
#pragma unroll
        for (int a = 0; a < 3; a++)
            if (!s_flag[a * 256 + jr * 64 + ii] && acc[a] <= ap3[a])
                contrib += softplusf(o4[a]);

        // block reduce -> 1 atomic per block
#pragma unroll
        for (int off = 16; off; off >>= 1)
            contrib += __shfl_xor_sync(0xffffffffu, contrib, off);
        if ((tid & 31) == 0) s_red[tid >> 5] = contrib;
        __syncthreads();
        if (tid == 0) {
            float tot = 0.f;
#pragma unroll
            for (int q = 0; q < 8; q++) tot += s_red[q];
            atomicAdd(&g_acc, tot);
        }
    } else {
        // ── Target-cell losses: one block (256 thr) per batch ──
        __shared__ float4 s_xywh[NT];
        __shared__ int    s_tc[NT], s_mask[NT], s_cls[NT], s_anc[NT], s_win[NT];

        int b = blockIdx.x - OBJ_BLOCKS;
        if (tid < NT) {
            TInfo t = target_info(labels, b, tid);
            s_xywh[tid] = make_float4(t.tx, t.ty, t.tw, t.th);
            s_tc[tid]   = t.cell;
            s_mask[tid] = t.mask ? 1 : 0;
            s_cls[tid]  = t.cls;
            s_anc[tid]  = t.a;
        }
        __syncthreads();
        if (tid < NT) {
            int win = s_mask[tid];
            int cell = s_tc[tid];
            for (int q = tid + 1; q < NT; q++)
                if (s_mask[q] && s_tc[q] == cell) win = 0;  // later target wins
            s_win[tid] = win;
        }
        __syncthreads();

        int wid  = tid >> 5;
        int lane = tid & 31;
        float sum = 0.f;
        for (int t = wid; t < NT; t += 8) {
            if (!s_win[t]) continue;
            int cell = s_tc[t];
            const float* o = out + (size_t)cell * NCH;
            for (int c = lane; c < NCLS; c += 32)
                sum += softplusf(o[5 + c]);
            if (lane == 0) {
                float4 tb = s_xywh[t];
                int aa = s_anc[t];
                float t0 = tb.x - floorf(tb.x);
                float t1 = tb.y - floorf(tb.y);
                float t2 = __logf(tb.z / c_aw[aa] + 1e-16f);
                float t3 = __logf(tb.w / c_ah[aa] + 1e-16f);
                float s  = sqrtf(2.f - tb.z * tb.w * (1.f / (NG * NG)));
                float o0 = o[0], o1 = o[1], o2 = o[2], o3 = o[3], oo4 = o[4];
                sum += softplusf(o0) - o0 * t0;          // loss_xy
                sum += softplusf(o1) - o1 * t1;
                float dw = (o2 - t2) * s, dh = (o3 - t3) * s;
                sum += 0.5f * (dw * dw + dh * dh);       // loss_wh
                sum += softplusf(oo4) - oo4;             // loss_obj (target=1)
                // cls: subtract o[5+k] once per DISTINCT class at this cell
                unsigned long long mlo = 0ull; unsigned mhi = 0u;
                for (int q = 0; q < NT; q++) {
                    if (s_mask[q] && s_tc[q] == cell) {
                        int k = s_cls[q];
                        if (k < 64) {
                            unsigned long long bit = 1ull << k;
                            if (!(mlo & bit)) { mlo |= bit; sum -= o[5 + k]; }
                        } else {
                            unsigned bit = 1u << (k - 64);
                            if (!(mhi & bit)) { mhi |= bit; sum -= o[5 + k]; }
                        }
                    }
                }
            }
        }
#pragma unroll
        for (int off = 16; off; off >>= 1)
            sum += __shfl_xor_sync(0xffffffffu, sum, off);
        if (lane == 0 && sum != 0.f) atomicAdd(&g_acc, sum);
    }

    // ── Grid completion: last block publishes the result and resets state ──
    __syncthreads();
    if (tid == 0) {
        __threadfence();
        if (atomicAdd(&g_cnt, 1u) == TOT_BLOCKS - 1) {
            __threadfence();
            res[0] = atomicAdd(&g_acc, 0.f);
            atomicExch(&g_acc, 0.f);
            atomicExch(&g_cnt, 0u);
        }
    }
}

extern "C" void kernel_launch(void* const* d_in, const int* in_sizes, int n_in,
                              void* d_out, int out_size) {
    const float* output = (const float*)d_in[0];
    const float* labels = (const float*)d_in[1];
    if (n_in >= 2 && in_sizes[0] < in_sizes[1]) {  // defensive: output is the big one
        const float* t = output; output = labels; labels = t;
    }
    float* res = (float*)d_out;

    k_one<<<TOT_BLOCKS, 256>>>(output, labels, res);
}

// round 12
// speedup vs baseline: 1.2737x; 1.2737x over previous
#include <cuda_runtime.h>

#define NB 16
#define NT 50
#define NG 64
#define NA 3
#define NCH 96
#define NCLS 91
#define NCELL (NB*NA*NG*NG)   /* 196608 */

#define OBJ_BLOCKS 384        /* 512 cells per block: (b, a, 8 jj rows, all ii) */
#define TGT_BLOCKS 16         /* one block per batch */
#define TOT_BLOCKS (OBJ_BLOCKS + TGT_BLOCKS)
#define BLK_PER_B  24

// ANCHORS / STRIDE(8)
__constant__ float c_aw[9] = {1.25f, 2.0f, 4.125f, 3.75f, 7.75f, 7.375f, 14.5f, 19.5f, 46.625f};
__constant__ float c_ah[9] = {1.625f, 3.75f, 2.875f, 7.625f, 5.625f, 14.875f, 11.25f, 24.75f, 40.75f};

// Grid-wide accumulator (zero-init at load; last block resets each call)
__device__ float    g_acc;
__device__ unsigned g_cnt;

__device__ __forceinline__ float softplusf(float x) {
    return fmaxf(x, 0.f) + __logf(1.f + __expf(-fabsf(x)));
}
__device__ __forceinline__ float sigmoidf(float x) {
    return __fdividef(1.f, 1.f + __expf(-x));
}

struct TInfo {
    float tx, ty, tw, th;
    int   a, cls, cell;
    bool  valid, mask;
};

// Division-free: argmax_k inter_k/den_k via cross-multiplication (dens > 0).
__device__ __forceinline__ TInfo target_info(const float* __restrict__ labels,
                                             int b, int tl) {
    const float* L = labels + (size_t)(b * NT + tl) * 5;
    float cls = L[0], x = L[1], y = L[2], w = L[3], h = L[4];
    TInfo r;
    r.valid = (cls + x + y + w + h) > 0.f;
    r.tx = x * NG; r.ty = y * NG; r.tw = w * NG; r.th = h * NG;
    float at = r.tw * r.th;
    float bin = -1.f, bden = 1.f;   // best inter/den; -1/1 loses to any k (inter>=0)
    int bi = 0;
#pragma unroll
    for (int k = 0; k < 9; k++) {
        float mw = fminf(r.tw, c_aw[k]);
        float mh = fminf(r.th, c_ah[k]);
        float inter = (mw > 0.f && mh > 0.f) ? mw * mh : 0.f;
        float den = at + c_aw[k] * c_ah[k] - inter;      // > 0
        if (inter * bden > bin * den) { bin = inter; bden = den; bi = k; }
    }
    r.a = bi % 3;
    r.mask = r.valid && (bi < 3);      // ANCH_MASK = [0,1,2] at SCALE=2
    int ii = (int)r.tx, jj = (int)r.ty;
    r.cell = ((b * NA + r.a) * NG + jj) * NG + ii;
    r.cls = (int)cls;
    return r;
}

__global__ void __launch_bounds__(512) k_one(const float* __restrict__ out,
                                             const float* __restrict__ labels,
                                             float* __restrict__ res) {
    int tid = threadIdx.x;

    if (blockIdx.x < OBJ_BLOCKS) {
        // ── Obj-loss scan (R8 geometry) + y-extent target pruning ──
        __shared__ float4 s_tb[NT];
        __shared__ float  s_a3[NT];
        __shared__ unsigned char s_flag[512];
        __shared__ int    s_idx[NT + 2];
        __shared__ int    s_cnt;
        __shared__ float  s_red[16];

        int base = blockIdx.x * 512;
        int b    = blockIdx.x / BLK_PER_B;
        int wb   = blockIdx.x % BLK_PER_B;
        int a    = wb >> 3;
        int jj0  = (wb & 7) * 8;
        int ii   = tid & 63;
        int jj   = jj0 + (tid >> 6);

        // Issue the cell loads FIRST (in flight during target staging)
        const float* o = out + (size_t)(base + tid) * NCH;
        float4 ov = __ldg(reinterpret_cast<const float4*>(o));  // ch0..3
        float  o4 = __ldg(o + 4);

        // Stage this batch's 50 target boxes; flag local target cells
        s_flag[tid & 511] = 0;
        if (tid == 0) s_cnt = 0;
        if (tid < NT) {
            TInfo t = target_info(labels, b, tid);
            if (t.valid) {
                s_tb[tid] = make_float4(t.tx - 0.5f * t.tw, t.ty - 0.5f * t.th,
                                        t.tx + 0.5f * t.tw, t.ty + 0.5f * t.th);
                s_a3[tid] = t.tw * t.th * (1.f / 3.f);
            } else {
                // finite sentinel: dxp=0, fmaf(0,-2e30,-1e30) = -1e30 (no NaN)
                s_tb[tid] = make_float4(1e30f, 1e30f, -1e30f, -1e30f);
                s_a3[tid] = 1e30f;
            }
            if (t.mask) {
                int local = t.cell - base;   // in range only for the owning block
                if (local >= 0 && local < 512) s_flag[local] = 1;
            }
        }

        // Pred box (dependent on the in-flight load)
        float px = sigmoidf(ov.x) + (float)ii;
        float py = sigmoidf(ov.y) + (float)jj;
        float pw = __expf(ov.z) * c_aw[a];
        float ph = __expf(ov.w) * c_ah[a];
        float ptlx = px - 0.5f * pw, pbrx = px + 0.5f * pw;
        float ptly = py - 0.5f * ph, pbry = py + 0.5f * ph;
        float ap3  = pw * ph * (1.f / 3.f);
        float sp4  = softplusf(o4);          // hoisted; selected at the end

        // Block-max ph for a conservative y-window
        float m = ph;
#pragma unroll
        for (int off = 16; off; off >>= 1)
            m = fmaxf(m, __shfl_xor_sync(0xffffffffu, m, off));
        if ((tid & 31) == 0) s_red[tid >> 5] = m;
        __syncthreads();

        // Compact the targets whose y-extent can overlap this block's rows
        if (tid < NT) {
            float phm = s_red[0];
#pragma unroll
            for (int k = 1; k < 16; k++) phm = fmaxf(phm, s_red[k]);
            float ymin = (float)jj0 - 0.5f * phm;
            float ymax = (float)(jj0 + 8) + 0.5f * phm;
            // dy>0 needs tb.tly < pbry (<= ymax) AND tb.bry > ptly (>= ymin)
            if (s_tb[tid].y < ymax && s_tb[tid].w > ymin) {
                int pos = atomicAdd(&s_cnt, 1);
                s_idx[pos] = tid;
            }
        }
        __syncthreads();
        int cnt  = s_cnt;
        int cntp = (cnt + 1) & ~1;
        if (tid == 0 && cntp != cnt) {
            // pad slot -> any invalid-style entry; reuse target 0's slot is wrong,
            // so write a sentinel index NT handled by dedicated smem below
            s_idx[cnt] = -1;
        }
        __syncthreads();

        // ignored  <=>  max_q( max(dx,0)*dy - at_q/3 ) > ap/3
        // Dual accumulators break the serial fmax chain.
        float acc0 = -1e30f, acc1 = -1e30f;
#pragma unroll 4
        for (int k = 0; k + 1 < cntp; k += 2) {
            int q0 = s_idx[k], q1 = s_idx[k + 1];
            {
                float4 tb = s_tb[q0]; float s3 = s_a3[q0];
                float dx  = fminf(pbrx, tb.z) - fmaxf(ptlx, tb.x);
                float dxp = fmaxf(dx, 0.f);
                float dy  = fminf(pbry, tb.w) - fmaxf(ptly, tb.y);
                acc0 = fmaxf(acc0, fmaf(dxp, dy, -s3));
            }
            if (q1 >= 0) {
                float4 tb = s_tb[q1]; float s3 = s_a3[q1];
                float dx  = fminf(pbrx, tb.z) - fmaxf(ptlx, tb.x);
                float dxp = fmaxf(dx, 0.f);
                float dy  = fminf(pbry, tb.w) - fmaxf(ptly, tb.y);
                acc1 = fmaxf(acc1, fmaf(dxp, dy, -s3));
            }
        }
        float acc = fmaxf(acc0, acc1);

        float contrib = (!s_flag[tid & 511] && acc <= ap3) ? sp4 : 0.f;

        // block reduce -> 1 atomic per block
#pragma unroll
        for (int off = 16; off; off >>= 1)
            contrib += __shfl_xor_sync(0xffffffffu, contrib, off);
        __syncthreads();                     // s_red reuse
        if ((tid & 31) == 0) s_red[tid >> 5] = contrib;
        __syncthreads();
        if (tid == 0) {
            float tot = 0.f;
#pragma unroll
            for (int q = 0; q < 16; q++) tot += s_red[q];
            atomicAdd(&g_acc, tot);
        }
    } else {
        // ── Target-cell losses: one block per batch ──
        __shared__ float4 s_xywh[NT];
        __shared__ int    s_tc[NT], s_mask[NT], s_cls[NT], s_anc[NT], s_win[NT];

        int b = blockIdx.x - OBJ_BLOCKS;
        if (tid < NT) {
            TInfo t = target_info(labels, b, tid);
            s_xywh[tid] = make_float4(t.tx, t.ty, t.tw, t.th);
            s_tc[tid]   = t.cell;
            s_mask[tid] = t.mask ? 1 : 0;
            s_cls[tid]  = t.cls;
            s_anc[tid]  = t.a;
        }
        __syncthreads();
        if (tid < NT) {
            int win = s_mask[tid];
            int cell = s_tc[tid];
            for (int q = tid + 1; q < NT; q++)
                if (s_mask[q] && s_tc[q] == cell) win = 0;  // later target wins
            s_win[tid] = win;
        }
        __syncthreads();

        int wid  = tid >> 5;
        int lane = tid & 31;
        float sum = 0.f;
        for (int t = wid; t < NT; t += 16) {
            if (!s_win[t]) continue;
            int cell = s_tc[t];
            const float* o = out + (size_t)cell * NCH;
            for (int c = lane; c < NCLS; c += 32)
                sum += softplusf(o[5 + c]);
            if (lane == 0) {
                float4 tb = s_xywh[t];
                int aa = s_anc[t];
                float t0 = tb.x - floorf(tb.x);
                float t1 = tb.y - floorf(tb.y);
                float t2 = __logf(tb.z / c_aw[aa] + 1e-16f);
                float t3 = __logf(tb.w / c_ah[aa] + 1e-16f);
                float s  = sqrtf(2.f - tb.z * tb.w * (1.f / (NG * NG)));
                float o0 = o[0], o1 = o[1], o2 = o[2], o3 = o[3], oo4 = o[4];
                sum += softplusf(o0) - o0 * t0;          // loss_xy
                sum += softplusf(o1) - o1 * t1;
                float dw = (o2 - t2) * s, dh = (o3 - t3) * s;
                sum += 0.5f * (dw * dw + dh * dh);       // loss_wh
                sum += softplusf(oo4) - oo4;             // loss_obj (target=1)
                // cls: subtract o[5+k] once per DISTINCT class at this cell
                unsigned long long mlo = 0ull; unsigned mhi = 0u;
                for (int q = 0; q < NT; q++) {
                    if (s_mask[q] && s_tc[q] == cell) {
                        int k = s_cls[q];
                        if (k < 64) {
                            unsigned long long bit = 1ull << k;
                            if (!(mlo & bit)) { mlo |= bit; sum -= o[5 + k]; }
                        } else {
                            unsigned bit = 1u << (k - 64);
                            if (!(mhi & bit)) { mhi |= bit; sum -= o[5 + k]; }
                        }
                    }
                }
            }
        }
#pragma unroll
        for (int off = 16; off; off >>= 1)
            sum += __shfl_xor_sync(0xffffffffu, sum, off);
        if (lane == 0 && sum != 0.f) atomicAdd(&g_acc, sum);
    }

    // ── Grid completion: last block publishes the result and resets state ──
    __syncthreads();
    if (tid == 0) {
        __threadfence();
        if (atomicAdd(&g_cnt, 1u) == TOT_BLOCKS - 1) {
            __threadfence();
            res[0] = atomicAdd(&g_acc, 0.f);
            atomicExch(&g_acc, 0.f);
            atomicExch(&g_cnt, 0u);
        }
    }
}

extern "C" void kernel_launch(void* const* d_in, const int* in_sizes, int n_in,
                              void* d_out, int out_size) {
    const float* output = (const float*)d_in[0];
    const float* labels = (const float*)d_in[1];
    if (n_in >= 2 && in_sizes[0] < in_sizes[1]) {  // defensive: output is the big one
        const float* t = output; output = labels; labels = t;
    }
    float* res = (float*)d_out;

    k_one<<<TOT_BLOCKS, 512>>>(output, labels, res);
}